// round 2
// baseline (speedup 1.0000x reference)
#include <cuda_runtime.h>
#include <math.h>

#define PRE   64
#define BATCH 1024
#define NNB   256
#define MASS  60.0f
#define BPB   4          // batches per block
#define FLD_BLOCKS (BATCH / BPB)   // 256

// accumulators: [0] = sum of energy_norm over (b,t); [1] = sum of squared error
__device__ float g_acc[2];

__global__ void init_kernel() {
    g_acc[0] = 0.0f;
    g_acc[1] = 0.0f;
}

// ---------------------------------------------------------------------------
// Field energy kernel: one block handles BPB batches, 64 threads per batch
// (one per timestep). Neighbours staged in shared with cos/sin precomputed.
// Inner loop: 256 neighbours, pure FMA + 2 MUFU per pair, no trig.
// ---------------------------------------------------------------------------
__global__ __launch_bounds__(256, 4)
void field_kernel(const float* __restrict__ out,       // (PRE, BATCH, 2)
                  const float* __restrict__ nb)        // (BATCH, NNB, 5)
{
    __shared__ float s_nx[BPB][NNB];
    __shared__ float s_ny[BPB][NNB];
    __shared__ float s_ca[BPB][NNB];
    __shared__ float s_sa[BPB][NNB];

    const int tid = threadIdx.x;          // 0..255
    const int b0  = blockIdx.x * BPB;

    // Cooperative neighbour staging + per-neighbour sincos (done ONCE per
    // block, amortized over 64 timesteps).
    for (int i = tid; i < BPB * NNB; i += 256) {
        const int bb = i >> 8;            // 0..3
        const int j  = i & (NNB - 1);
        const float* p = nb + ((size_t)(b0 + bb) * NNB + j) * 5;
        const float nx = p[0];
        const float ny = p[1];
        const float ang = p[4];
        float sa, ca;
        sincosf(ang, &sa, &ca);
        s_nx[bb][j] = nx;
        s_ny[bb][j] = ny;
        s_ca[bb][j] = ca;
        s_sa[bb][j] = sa;
    }
    __syncthreads();

    const int bb = tid >> 6;              // 0..3  (warp-uniform)
    const int t  = tid & 63;
    const int b  = b0 + bb;

    // output layout (t, b, c): index = (t*BATCH + b)*2 + c
    const float2 p2 = *reinterpret_cast<const float2*>(out + ((size_t)t * BATCH + b) * 2);
    const float px = p2.x;
    const float py = p2.y;

    float ex = 0.0f, ey = 0.0f;
    #pragma unroll 8
    for (int j = 0; j < NNB; ++j) {
        const float dx = px - s_nx[bb][j];
        const float dy = py - s_ny[bb][j];
        const float ca = s_ca[bb][j];
        const float sa = s_sa[bb][j];
        const float x_ = fmaf(ca, dx, sa * dy);
        const float y_ = fmaf(ca, dy, -sa * dx);
        const float x2 = x_ * x_;
        const float y2 = y_ * y_;
        // x^6 + y^6 + 6
        const float den = fmaf(x2 * x2, x2, fmaf(y2 * y2, y2, 6.0f));
        const float r2  = fmaf(dx, dx, dy * dy);
        // energy_i * (1/r): cos(atan2(-dy,-dx)) = -dx/r, sin = -dy/r.
        // Sign dropped — it cancels in sqrt(ex^2+ey^2).
        const float w = __fdividef(MASS, den) * rsqrtf(r2);
        ex = fmaf(w, dx, ex);
        ey = fmaf(w, dy, ey);
    }

    float v = sqrtf(fmaf(ex, ex, ey * ey));   // energy_norm for (b, t)

    // block reduce 256 -> 1
    #pragma unroll
    for (int o = 16; o; o >>= 1)
        v += __shfl_xor_sync(0xffffffffu, v, o);

    __shared__ float s_red[8];
    if ((tid & 31) == 0) s_red[tid >> 5] = v;
    __syncthreads();
    if (tid < 8) {
        float s = s_red[tid];
        #pragma unroll
        for (int o = 4; o; o >>= 1)
            s += __shfl_xor_sync(0x000000ffu, s, o);
        if (tid == 0) atomicAdd(&g_acc[0], s);
    }
}

// ---------------------------------------------------------------------------
// MSE kernel: grid-stride sum of squared error over PRE*BATCH*2 floats.
// ---------------------------------------------------------------------------
__global__ void mse_kernel(const float* __restrict__ o,
                           const float* __restrict__ tg)
{
    const int n = PRE * BATCH * 2;
    float s = 0.0f;
    for (int i = blockIdx.x * blockDim.x + threadIdx.x; i < n;
         i += gridDim.x * blockDim.x) {
        const float d = o[i] - tg[i];
        s = fmaf(d, d, s);
    }
    #pragma unroll
    for (int o2 = 16; o2; o2 >>= 1)
        s += __shfl_xor_sync(0xffffffffu, s, o2);

    __shared__ float s_red[8];
    const int tid = threadIdx.x;
    if ((tid & 31) == 0) s_red[tid >> 5] = s;
    __syncthreads();
    if (tid < 8) {
        float v = s_red[tid];
        #pragma unroll
        for (int o2 = 4; o2; o2 >>= 1)
            v += __shfl_xor_sync(0x000000ffu, v, o2);
        if (tid == 0) atomicAdd(&g_acc[1], v);
    }
}

__global__ void finalize_kernel(float* __restrict__ dst) {
    const float inv_mse = 1.0f / (float)(PRE * BATCH * 2);
    const float inv_fe  = 1.0f / (float)(PRE * BATCH);
    dst[0] = g_acc[1] * inv_mse + g_acc[0] * inv_fe;
}

extern "C" void kernel_launch(void* const* d_in, const int* in_sizes, int n_in,
                              void* d_out, int out_size)
{
    const float* output     = (const float*)d_in[0];   // (64, 1024, 2)
    const float* target     = (const float*)d_in[1];   // (64, 1024, 2)
    const float* neighbours = (const float*)d_in[2];   // (1024, 256, 5)
    float* out = (float*)d_out;

    init_kernel<<<1, 1>>>();
    field_kernel<<<FLD_BLOCKS, 256>>>(output, neighbours);
    mse_kernel<<<64, 256>>>(output, target);
    finalize_kernel<<<1, 1>>>(out);
}

// round 3
// speedup vs baseline: 1.1079x; 1.1079x over previous
#include <cuda_runtime.h>
#include <math.h>
#include <stdint.h>

#define PRE    64
#define BATCH  1024
#define NNB    256
#define NPAIR  (NNB / 2)
#define MASSF  60.0f
#define NBLK   BATCH          // 1024 blocks, one batch each
#define NTHR   64             // one thread per timestep

// accumulators: [0] = sum energy_norm, [1] = sum squared error
__device__ float    g_acc[2] = {0.0f, 0.0f};
__device__ unsigned g_cnt    = 0;

// ---------------- packed f32x2 helpers (Blackwell) ----------------
static __device__ __forceinline__ uint64_t fpack(float a, float b) {
    uint64_t r; asm("mov.b64 %0,{%1,%2};" : "=l"(r) : "f"(a), "f"(b)); return r;
}
static __device__ __forceinline__ void funpack(uint64_t p, float& a, float& b) {
    asm("mov.b64 {%0,%1},%2;" : "=f"(a), "=f"(b) : "l"(p));
}
static __device__ __forceinline__ uint64_t padd(uint64_t a, uint64_t b) {
    uint64_t r; asm("add.rn.f32x2 %0,%1,%2;" : "=l"(r) : "l"(a), "l"(b)); return r;
}
static __device__ __forceinline__ uint64_t pmul(uint64_t a, uint64_t b) {
    uint64_t r; asm("mul.rn.f32x2 %0,%1,%2;" : "=l"(r) : "l"(a), "l"(b)); return r;
}
static __device__ __forceinline__ uint64_t pfma(uint64_t a, uint64_t b, uint64_t c) {
    uint64_t r; asm("fma.rn.f32x2 %0,%1,%2,%3;" : "=l"(r) : "l"(a), "l"(b), "l"(c)); return r;
}
static __device__ __forceinline__ uint64_t prsqrt(uint64_t m) {
    float a, b; funpack(m, a, b);
    float ra, rb;
    asm("rsqrt.approx.f32 %0,%1;" : "=f"(ra) : "f"(a));
    asm("rsqrt.approx.f32 %0,%1;" : "=f"(rb) : "f"(b));
    return fpack(ra, rb);
}

// ---------------------------------------------------------------------------
// One fused kernel. Block b owns batch b: stages its 256 neighbours (packed
// as 128 f32x2 pairs, sincos precomputed), each of the 64 threads handles one
// timestep. MSE is folded in (2 elements/thread, coalesced). Last finished
// block finalizes to d_out and resets the accumulators for the next replay.
// Inner loop per neighbour-pair: 18 f32x2 fma-pipe ops + 2 MUFU.RSQ + 5 LDS.64.
// Trig identity: energy_i*(cos,sin)(atan2(-dy,-dx)) = -w*(dx,dy) with
// w = MASS * rsqrt(den^2 * r2); the sign cancels in sqrt(ex^2+ey^2).
// ---------------------------------------------------------------------------
__global__ __launch_bounds__(NTHR)
void fused_kernel(const float* __restrict__ out,   // (PRE, BATCH, 2)
                  const float* __restrict__ tgt,   // (PRE, BATCH, 2)
                  const float* __restrict__ nb,    // (BATCH, NNB, 5)
                  float* __restrict__ dst)
{
    __shared__ uint64_t s_mnx[NPAIR];   // (-nx_2p, -nx_{2p+1})
    __shared__ uint64_t s_mny[NPAIR];
    __shared__ uint64_t s_ca [NPAIR];
    __shared__ uint64_t s_sa [NPAIR];
    __shared__ uint64_t s_nsa[NPAIR];
    __shared__ float    s_red[4];

    const int tid = threadIdx.x;        // timestep 0..63
    const int b   = blockIdx.x;         // batch

    // ---- MSE slice: thread covers 2 consecutive floats, coalesced ----
    float msum;
    {
        const int mi = b * NTHR + tid;  // PRE*BATCH float2 elements total
        const float2 o2 = ((const float2*)out)[mi];
        const float2 t2 = ((const float2*)tgt)[mi];
        const float d0 = o2.x - t2.x;
        const float d1 = o2.y - t2.y;
        msum = fmaf(d0, d0, d1 * d1);
    }

    // ---- stage neighbours: pack pairs, precompute sincos ----
    {
        const float* base = nb + (size_t)b * NNB * 5;
        for (int p = tid; p < NPAIR; p += NTHR) {
            const float* q = base + (size_t)(2 * p) * 5;
            const float nx0 = q[0], ny0 = q[1], a0 = q[4];
            const float nx1 = q[5], ny1 = q[6], a1 = q[9];
            float sa0, ca0, sa1, ca1;
            __sincosf(a0, &sa0, &ca0);
            __sincosf(a1, &sa1, &ca1);
            s_mnx[p] = fpack(-nx0, -nx1);
            s_mny[p] = fpack(-ny0, -ny1);
            s_ca [p] = fpack( ca0,  ca1);
            s_sa [p] = fpack( sa0,  sa1);
            s_nsa[p] = fpack(-sa0, -sa1);
        }
    }
    __syncthreads();

    // ---- field energy for (batch b, timestep tid) ----
    const float2 pp = ((const float2*)out)[(size_t)tid * BATCH + b];
    const uint64_t px2   = fpack(pp.x, pp.x);
    const uint64_t py2   = fpack(pp.y, pp.y);
    const uint64_t six2  = fpack(6.0f, 6.0f);
    const uint64_t mass2 = fpack(MASSF, MASSF);

    uint64_t ax = fpack(0.0f, 0.0f);
    uint64_t ay = fpack(0.0f, 0.0f);

    #pragma unroll 4
    for (int p = 0; p < NPAIR; ++p) {
        const uint64_t mnx = s_mnx[p];
        const uint64_t mny = s_mny[p];
        const uint64_t ca  = s_ca [p];
        const uint64_t sa  = s_sa [p];
        const uint64_t nsa = s_nsa[p];

        const uint64_t dx = padd(px2, mnx);
        const uint64_t dy = padd(py2, mny);
        const uint64_t x_ = pfma(ca, dx, pmul(sa,  dy));
        const uint64_t y_ = pfma(ca, dy, pmul(nsa, dx));
        const uint64_t x2 = pmul(x_, x_);
        const uint64_t y2 = pmul(y_, y_);
        const uint64_t den = pfma(pmul(x2, x2), x2,
                             pfma(pmul(y2, y2), y2, six2));
        const uint64_t r2  = pfma(dx, dx, pmul(dy, dy));
        const uint64_t m   = pmul(pmul(den, den), r2);
        const uint64_t w   = pmul(mass2, prsqrt(m));
        ax = pfma(w, dx, ax);
        ay = pfma(w, dy, ay);
    }

    float ex0, ex1, ey0, ey1;
    funpack(ax, ex0, ex1);
    funpack(ay, ey0, ey1);
    const float ex = ex0 + ex1;
    const float ey = ey0 + ey1;
    float v = sqrtf(fmaf(ex, ex, ey * ey));

    // ---- reduce v and msum across the 2 warps ----
    #pragma unroll
    for (int o = 16; o; o >>= 1) {
        v    += __shfl_xor_sync(0xffffffffu, v,    o);
        msum += __shfl_xor_sync(0xffffffffu, msum, o);
    }
    if ((tid & 31) == 0) {
        s_red[(tid >> 5) * 2 + 0] = v;
        s_red[(tid >> 5) * 2 + 1] = msum;
    }
    __syncthreads();

    if (tid == 0) {
        const float fv = s_red[0] + s_red[2];
        const float fm = s_red[1] + s_red[3];
        atomicAdd(&g_acc[0], fv);
        atomicAdd(&g_acc[1], fm);
        __threadfence();
        const unsigned r = atomicAdd(&g_cnt, 1u);
        if (r == (unsigned)(NBLK - 1)) {
            __threadfence();
            const float fe = *((volatile float*)&g_acc[0]);
            const float mm = *((volatile float*)&g_acc[1]);
            dst[0] = mm * (1.0f / (float)(PRE * BATCH * 2))
                   + fe * (1.0f / (float)(PRE * BATCH));
            g_acc[0] = 0.0f;
            g_acc[1] = 0.0f;
            __threadfence();
            g_cnt = 0;
        }
    }
}

extern "C" void kernel_launch(void* const* d_in, const int* in_sizes, int n_in,
                              void* d_out, int out_size)
{
    const float* output     = (const float*)d_in[0];   // (64, 1024, 2)
    const float* target     = (const float*)d_in[1];   // (64, 1024, 2)
    const float* neighbours = (const float*)d_in[2];   // (1024, 256, 5)
    float* dst = (float*)d_out;

    fused_kernel<<<NBLK, NTHR>>>(output, target, neighbours, dst);
}

// round 4
// speedup vs baseline: 1.3108x; 1.1831x over previous
#include <cuda_runtime.h>
#include <math.h>
#include <stdint.h>

#define PRE    64
#define BATCH  1024
#define NNB    256
#define NPAIR  (NNB / 2)     // 128 f32x2 neighbour pairs per batch
#define MASSF  60.0f
#define NBLK   BATCH         // 1024 blocks, one batch each
#define NTHR   256           // 4 threads per (batch, timestep)

// accumulators: [0] = 4 * sum energy_norm, [1] = sum squared error
__device__ float    g_acc[2] = {0.0f, 0.0f};
__device__ unsigned g_cnt    = 0;

// ---------------- packed f32x2 helpers (Blackwell) ----------------
static __device__ __forceinline__ uint64_t fpack(float a, float b) {
    uint64_t r; asm("mov.b64 %0,{%1,%2};" : "=l"(r) : "f"(a), "f"(b)); return r;
}
static __device__ __forceinline__ uint64_t upack(uint32_t a, uint32_t b) {
    uint64_t r; asm("mov.b64 %0,{%1,%2};" : "=l"(r) : "r"(a), "r"(b)); return r;
}
static __device__ __forceinline__ void funpack(uint64_t p, float& a, float& b) {
    asm("mov.b64 {%0,%1},%2;" : "=f"(a), "=f"(b) : "l"(p));
}
static __device__ __forceinline__ uint64_t padd(uint64_t a, uint64_t b) {
    uint64_t r; asm("add.rn.f32x2 %0,%1,%2;" : "=l"(r) : "l"(a), "l"(b)); return r;
}
static __device__ __forceinline__ uint64_t pmul(uint64_t a, uint64_t b) {
    uint64_t r; asm("mul.rn.f32x2 %0,%1,%2;" : "=l"(r) : "l"(a), "l"(b)); return r;
}
static __device__ __forceinline__ uint64_t pfma(uint64_t a, uint64_t b, uint64_t c) {
    uint64_t r; asm("fma.rn.f32x2 %0,%1,%2,%3;" : "=l"(r) : "l"(a), "l"(b), "l"(c)); return r;
}
static __device__ __forceinline__ uint64_t prsqrt(uint64_t m) {
    float a, b; funpack(m, a, b);
    float ra, rb;
    asm("rsqrt.approx.f32 %0,%1;" : "=f"(ra) : "f"(a));
    asm("rsqrt.approx.f32 %0,%1;" : "=f"(rb) : "f"(b));
    return fpack(ra, rb);
}

// ---------------------------------------------------------------------------
// Fused kernel. Block b = batch b (256 threads): thread = (t = tid>>2,
// c = tid&3); thread handles pairs p = 4i + c (i = 0..31).
// Math per pair (all f32x2, 2 neighbours/lane):
//   dx = px - nx, dy = py - ny
//   r2 = dx^2 + dy^2                       (rotation-invariant)
//   x_ = ca*dx + sa*dy,  x2 = x_^2
//   y2 = r2 - x2                           (y_ rotation eliminated)
//   den = x2^3 + y2^3 + 6
//   w = MASS * rsqrt(den^2 * r2)           (|e_i|/r; trig of atan2 cancels)
//   ex += w*dx, ey += w*dy                 (global sign cancels in the norm)
// 17 FFMA2 + 2 LDS.128 + 2 MUFU.RSQ per pair-iteration.
// ---------------------------------------------------------------------------
__global__ __launch_bounds__(NTHR)
void fused_kernel(const float* __restrict__ out,   // (PRE, BATCH, 2)
                  const float* __restrict__ tgt,   // (PRE, BATCH, 2)
                  const float* __restrict__ nb,    // (BATCH, NNB, 5)
                  float* __restrict__ dst)
{
    __shared__ uint4 s_xy[NPAIR];   // {-nx0,-nx1,-ny0,-ny1} (float bits)
    __shared__ uint4 s_cs[NPAIR];   // { ca0, ca1, sa0, sa1}
    __shared__ float s_red[16];

    const int tid = threadIdx.x;
    const int b   = blockIdx.x;

    // ---- MSE slice: one float per thread (first 131072 global threads) ----
    float msum = 0.0f;
    {
        const int g = b * NTHR + tid;
        if (g < PRE * BATCH * 2) {
            const float d = out[g] - tgt[g];
            msum = d * d;
        }
    }

    // ---- stage neighbours: pack pairs, precompute sincos ----
    {
        const float* base = nb + (size_t)b * NNB * 5;
        for (int p = tid; p < NPAIR; p += NTHR) {
            const float* q = base + (size_t)(2 * p) * 5;
            const float nx0 = q[0], ny0 = q[1], a0 = q[4];
            const float nx1 = q[5], ny1 = q[6], a1 = q[9];
            float sa0, ca0, sa1, ca1;
            __sincosf(a0, &sa0, &ca0);
            __sincosf(a1, &sa1, &ca1);
            uint4 xy, cs;
            xy.x = __float_as_uint(-nx0); xy.y = __float_as_uint(-nx1);
            xy.z = __float_as_uint(-ny0); xy.w = __float_as_uint(-ny1);
            cs.x = __float_as_uint( ca0); cs.y = __float_as_uint( ca1);
            cs.z = __float_as_uint( sa0); cs.w = __float_as_uint( sa1);
            s_xy[p] = xy;
            s_cs[p] = cs;
        }
    }
    __syncthreads();

    const int c = tid & 3;            // pair-chunk lane
    const int t = tid >> 2;           // timestep 0..63

    const float2 pp = ((const float2*)out)[(size_t)t * BATCH + b];
    const uint64_t px2   = fpack(pp.x, pp.x);
    const uint64_t py2   = fpack(pp.y, pp.y);
    const uint64_t six2  = fpack(6.0f, 6.0f);
    const uint64_t mone2 = fpack(-1.0f, -1.0f);
    const uint64_t mass2 = fpack(MASSF, MASSF);

    uint64_t ax = 0ull;               // +0.0f, +0.0f
    uint64_t ay = 0ull;

    #pragma unroll 8
    for (int i = 0; i < NPAIR / 4; ++i) {
        const int p = (i << 2) | c;
        const uint4 xy = s_xy[p];
        const uint4 cs = s_cs[p];
        const uint64_t mnx = upack(xy.x, xy.y);
        const uint64_t mny = upack(xy.z, xy.w);
        const uint64_t ca  = upack(cs.x, cs.y);
        const uint64_t sa  = upack(cs.z, cs.w);

        const uint64_t dx = padd(px2, mnx);
        const uint64_t dy = padd(py2, mny);
        const uint64_t r2 = pfma(dx, dx, pmul(dy, dy));
        const uint64_t x_ = pfma(ca, dx, pmul(sa, dy));
        const uint64_t x2 = pmul(x_, x_);
        const uint64_t y2 = pfma(x2, mone2, r2);
        const uint64_t den = pfma(pmul(x2, x2), x2,
                             pfma(pmul(y2, y2), y2, six2));
        const uint64_t m  = pmul(pmul(den, den), r2);
        const uint64_t w  = pmul(mass2, prsqrt(m));
        ax = pfma(w, dx, ax);
        ay = pfma(w, dy, ay);
    }

    // combine packed halves, then reduce over the 4 c-lanes
    float ex0, ex1, ey0, ey1;
    funpack(ax, ex0, ex1);
    funpack(ay, ey0, ey1);
    float ex = ex0 + ex1;
    float ey = ey0 + ey1;
    ex += __shfl_xor_sync(0xffffffffu, ex, 1);
    ex += __shfl_xor_sync(0xffffffffu, ex, 2);
    ey += __shfl_xor_sync(0xffffffffu, ey, 1);
    ey += __shfl_xor_sync(0xffffffffu, ey, 2);

    // v is now identical on the 4 c-lanes -> warp sum counts each (b,t) 4x;
    // compensated by the 1/4 in the finalize constant.
    float v = sqrtf(fmaf(ex, ex, ey * ey));

    #pragma unroll
    for (int o = 16; o; o >>= 1) {
        v    += __shfl_xor_sync(0xffffffffu, v,    o);
        msum += __shfl_xor_sync(0xffffffffu, msum, o);
    }
    if ((tid & 31) == 0) {
        s_red[(tid >> 5) * 2 + 0] = v;
        s_red[(tid >> 5) * 2 + 1] = msum;
    }
    __syncthreads();

    if (tid == 0) {
        float fv = 0.0f, fm = 0.0f;
        #pragma unroll
        for (int w8 = 0; w8 < 8; ++w8) {
            fv += s_red[w8 * 2 + 0];
            fm += s_red[w8 * 2 + 1];
        }
        atomicAdd(&g_acc[0], fv);
        atomicAdd(&g_acc[1], fm);
        __threadfence();
        const unsigned r = atomicAdd(&g_cnt, 1u);
        if (r == (unsigned)(NBLK - 1)) {
            __threadfence();
            const float fe = *((volatile float*)&g_acc[0]);   // 4x over-counted
            const float mm = *((volatile float*)&g_acc[1]);
            dst[0] = mm * (1.0f / (float)(PRE * BATCH * 2))
                   + fe * (1.0f / (4.0f * (float)(PRE * BATCH)));
            g_acc[0] = 0.0f;
            g_acc[1] = 0.0f;
            __threadfence();
            g_cnt = 0;
        }
    }
}

extern "C" void kernel_launch(void* const* d_in, const int* in_sizes, int n_in,
                              void* d_out, int out_size)
{
    const float* output     = (const float*)d_in[0];   // (64, 1024, 2)
    const float* target     = (const float*)d_in[1];   // (64, 1024, 2)
    const float* neighbours = (const float*)d_in[2];   // (1024, 256, 5)
    float* dst = (float*)d_out;

    fused_kernel<<<NBLK, NTHR>>>(output, target, neighbours, dst);
}

// round 5
// speedup vs baseline: 1.3168x; 1.0046x over previous
#include <cuda_runtime.h>
#include <math.h>
#include <stdint.h>

#define PRE    64
#define BATCH  1024
#define NNB    256
#define NPAIR  (NNB / 2)     // 128 f32x2 neighbour pairs per batch
#define MASSF  60.0f
#define NBLK   BATCH         // 1024 blocks, one batch each
#define NTHR   256           // 8 c-lanes x 32 timestep-pairs

// accumulators: [0] = 8 * sum energy_norm / MASS, [1] = sum squared error
__device__ float    g_acc[2] = {0.0f, 0.0f};
__device__ unsigned g_cnt    = 0;

// ---------------- packed f32x2 helpers (Blackwell) ----------------
static __device__ __forceinline__ uint64_t fpack(float a, float b) {
    uint64_t r; asm("mov.b64 %0,{%1,%2};" : "=l"(r) : "f"(a), "f"(b)); return r;
}
static __device__ __forceinline__ void funpack(uint64_t p, float& a, float& b) {
    asm("mov.b64 {%0,%1},%2;" : "=f"(a), "=f"(b) : "l"(p));
}
static __device__ __forceinline__ uint64_t padd(uint64_t a, uint64_t b) {
    uint64_t r; asm("add.rn.f32x2 %0,%1,%2;" : "=l"(r) : "l"(a), "l"(b)); return r;
}
static __device__ __forceinline__ uint64_t pmul(uint64_t a, uint64_t b) {
    uint64_t r; asm("mul.rn.f32x2 %0,%1,%2;" : "=l"(r) : "l"(a), "l"(b)); return r;
}
static __device__ __forceinline__ uint64_t pfma(uint64_t a, uint64_t b, uint64_t c) {
    uint64_t r; asm("fma.rn.f32x2 %0,%1,%2,%3;" : "=l"(r) : "l"(a), "l"(b), "l"(c)); return r;
}
static __device__ __forceinline__ uint64_t prsqrt(uint64_t m) {
    float a, b; funpack(m, a, b);
    float ra, rb;
    asm("rsqrt.approx.f32 %0,%1;" : "=f"(ra) : "f"(a));
    asm("rsqrt.approx.f32 %0,%1;" : "=f"(rb) : "f"(b));
    return fpack(ra, rb);
}

// ---------------------------------------------------------------------------
// Fused kernel. Block b = batch b (256 threads). Thread = (tg = tid>>3 ->
// timesteps {2tg, 2tg+1}, c = tid&7 -> pairs p = 8i+c, i = 0..15).
// Each iteration loads one neighbour pair-record (2x LDS.128, zero repack)
// and evaluates BOTH timesteps: 2 x 16 packed f32x2 fma-pipe ops + 4 MUFU.
// Math per (t, pair):
//   dx=px-nx, dy=py-ny; r2=dx^2+dy^2; x_=ca*dx+sa*dy; x2=x_^2; y2=r2-x2;
//   den=x2^3+y2^3+6; w=rsqrt(den^2*r2);       (MASS folded into finalize)
//   ex+=w*dx, ey+=w*dy                        (atan2 trig & signs cancel)
// v is identical across the 8 c-lanes -> warp-sum overcounts 8x; folded
// into the finalize constant together with MASS.
// ---------------------------------------------------------------------------
__global__ __launch_bounds__(NTHR, 7)
void fused_kernel(const float* __restrict__ out,   // (PRE, BATCH, 2)
                  const float* __restrict__ tgt,   // (PRE, BATCH, 2)
                  const float* __restrict__ nb,    // (BATCH, NNB, 5)
                  float* __restrict__ dst)
{
    __shared__ ulonglong2 s_xy[NPAIR];  // {fpack(-nx0,-nx1), fpack(-ny0,-ny1)}
    __shared__ ulonglong2 s_cs[NPAIR];  // {fpack( ca0, ca1), fpack( sa0, sa1)}
    __shared__ float s_red[16];

    const int tid = threadIdx.x;
    const int b   = blockIdx.x;

    // ---- MSE slice: one float per thread (first 131072 global threads) ----
    float msum = 0.0f;
    {
        const int g = b * NTHR + tid;
        if (g < PRE * BATCH * 2) {
            const float d = out[g] - tgt[g];
            msum = d * d;
        }
    }

    // ---- stage neighbours: pack pairs, precompute sincos ----
    if (tid < NPAIR) {
        const int p = tid;
        const float* q = nb + ((size_t)b * NNB + 2 * p) * 5;
        const float nx0 = q[0], ny0 = q[1], a0 = q[4];
        const float nx1 = q[5], ny1 = q[6], a1 = q[9];
        float sa0, ca0, sa1, ca1;
        __sincosf(a0, &sa0, &ca0);
        __sincosf(a1, &sa1, &ca1);
        ulonglong2 xy, cs;
        xy.x = fpack(-nx0, -nx1);
        xy.y = fpack(-ny0, -ny1);
        cs.x = fpack( ca0,  ca1);
        cs.y = fpack( sa0,  sa1);
        s_xy[p] = xy;
        s_cs[p] = cs;
    }
    __syncthreads();

    const int c  = tid & 7;           // pair-chunk lane (8 chunks of 16)
    const int tg = tid >> 3;          // timestep pair 0..31
    const int ta = 2 * tg;
    const int tb = 2 * tg + 1;

    const float2 pa = ((const float2*)out)[(size_t)ta * BATCH + b];
    const float2 pb = ((const float2*)out)[(size_t)tb * BATCH + b];
    const uint64_t pxa = fpack(pa.x, pa.x), pya = fpack(pa.y, pa.y);
    const uint64_t pxb = fpack(pb.x, pb.x), pyb = fpack(pb.y, pb.y);
    const uint64_t six2  = fpack(6.0f, 6.0f);
    const uint64_t mone2 = fpack(-1.0f, -1.0f);

    uint64_t axa = 0ull, aya = 0ull;  // (+0.0f, +0.0f)
    uint64_t axb = 0ull, ayb = 0ull;

    #pragma unroll 4
    for (int i = 0; i < NPAIR / 8; ++i) {
        const int p = (i << 3) | c;
        const ulonglong2 xy = s_xy[p];
        const ulonglong2 cs = s_cs[p];

        {   // timestep ta
            const uint64_t dx = padd(pxa, xy.x);
            const uint64_t dy = padd(pya, xy.y);
            const uint64_t r2 = pfma(dx, dx, pmul(dy, dy));
            const uint64_t x_ = pfma(cs.x, dx, pmul(cs.y, dy));
            const uint64_t x2 = pmul(x_, x_);
            const uint64_t y2 = pfma(x2, mone2, r2);
            const uint64_t den = pfma(pmul(x2, x2), x2,
                                 pfma(pmul(y2, y2), y2, six2));
            const uint64_t w = prsqrt(pmul(pmul(den, den), r2));
            axa = pfma(w, dx, axa);
            aya = pfma(w, dy, aya);
        }
        {   // timestep tb
            const uint64_t dx = padd(pxb, xy.x);
            const uint64_t dy = padd(pyb, xy.y);
            const uint64_t r2 = pfma(dx, dx, pmul(dy, dy));
            const uint64_t x_ = pfma(cs.x, dx, pmul(cs.y, dy));
            const uint64_t x2 = pmul(x_, x_);
            const uint64_t y2 = pfma(x2, mone2, r2);
            const uint64_t den = pfma(pmul(x2, x2), x2,
                                 pfma(pmul(y2, y2), y2, six2));
            const uint64_t w = prsqrt(pmul(pmul(den, den), r2));
            axb = pfma(w, dx, axb);
            ayb = pfma(w, dy, ayb);
        }
    }

    // combine packed halves, reduce over the 8 c-lanes
    float t0, t1;
    funpack(axa, t0, t1); float exa = t0 + t1;
    funpack(aya, t0, t1); float eya = t0 + t1;
    funpack(axb, t0, t1); float exb = t0 + t1;
    funpack(ayb, t0, t1); float eyb = t0 + t1;
    #pragma unroll
    for (int o = 1; o <= 4; o <<= 1) {
        exa += __shfl_xor_sync(0xffffffffu, exa, o);
        eya += __shfl_xor_sync(0xffffffffu, eya, o);
        exb += __shfl_xor_sync(0xffffffffu, exb, o);
        eyb += __shfl_xor_sync(0xffffffffu, eyb, o);
    }

    // identical on 8 c-lanes -> warp sum overcounts 8x (folded in finalize)
    float v = sqrtf(fmaf(exa, exa, eya * eya))
            + sqrtf(fmaf(exb, exb, eyb * eyb));

    #pragma unroll
    for (int o = 16; o; o >>= 1) {
        v    += __shfl_xor_sync(0xffffffffu, v,    o);
        msum += __shfl_xor_sync(0xffffffffu, msum, o);
    }
    if ((tid & 31) == 0) {
        s_red[(tid >> 5) * 2 + 0] = v;
        s_red[(tid >> 5) * 2 + 1] = msum;
    }
    __syncthreads();

    if (tid == 0) {
        float fv = 0.0f, fm = 0.0f;
        #pragma unroll
        for (int w8 = 0; w8 < 8; ++w8) {
            fv += s_red[w8 * 2 + 0];
            fm += s_red[w8 * 2 + 1];
        }
        atomicAdd(&g_acc[0], fv);
        atomicAdd(&g_acc[1], fm);
        __threadfence();
        const unsigned r = atomicAdd(&g_cnt, 1u);
        if (r == (unsigned)(NBLK - 1)) {
            __threadfence();
            const float fe = *((volatile float*)&g_acc[0]);   // 8x, /MASS
            const float mm = *((volatile float*)&g_acc[1]);
            dst[0] = mm * (1.0f / (float)(PRE * BATCH * 2))
                   + fe * (MASSF / (8.0f * (float)(PRE * BATCH)));
            g_acc[0] = 0.0f;
            g_acc[1] = 0.0f;
            __threadfence();
            g_cnt = 0;
        }
    }
}

extern "C" void kernel_launch(void* const* d_in, const int* in_sizes, int n_in,
                              void* d_out, int out_size)
{
    const float* output     = (const float*)d_in[0];   // (64, 1024, 2)
    const float* target     = (const float*)d_in[1];   // (64, 1024, 2)
    const float* neighbours = (const float*)d_in[2];   // (1024, 256, 5)
    float* dst = (float*)d_out;

    fused_kernel<<<NBLK, NTHR>>>(output, target, neighbours, dst);
}

// round 6
// speedup vs baseline: 1.3250x; 1.0062x over previous
#include <cuda_runtime.h>
#include <math.h>
#include <stdint.h>

#define PRE    64
#define BATCH  1024
#define NNB    256
#define NPAIR  (NNB / 2)     // 128 f32x2 neighbour pairs per batch
#define MASSF  60.0f
#define BPB    2             // batches per block
#define NBLK   (BATCH / BPB) // 512 blocks
#define NTHR   256           // 128 threads per batch: 4 c-lanes x 32 t-pairs

// accumulators: [0] = 4 * sum energy_norm / MASS, [1] = sum squared error
__device__ float    g_acc[2] = {0.0f, 0.0f};
__device__ unsigned g_cnt    = 0;

// ---------------- packed f32x2 helpers (Blackwell) ----------------
static __device__ __forceinline__ uint64_t fpack(float a, float b) {
    uint64_t r; asm("mov.b64 %0,{%1,%2};" : "=l"(r) : "f"(a), "f"(b)); return r;
}
static __device__ __forceinline__ void funpack(uint64_t p, float& a, float& b) {
    asm("mov.b64 {%0,%1},%2;" : "=f"(a), "=f"(b) : "l"(p));
}
static __device__ __forceinline__ uint64_t padd(uint64_t a, uint64_t b) {
    uint64_t r; asm("add.rn.f32x2 %0,%1,%2;" : "=l"(r) : "l"(a), "l"(b)); return r;
}
static __device__ __forceinline__ uint64_t pmul(uint64_t a, uint64_t b) {
    uint64_t r; asm("mul.rn.f32x2 %0,%1,%2;" : "=l"(r) : "l"(a), "l"(b)); return r;
}
static __device__ __forceinline__ uint64_t pfma(uint64_t a, uint64_t b, uint64_t c) {
    uint64_t r; asm("fma.rn.f32x2 %0,%1,%2,%3;" : "=l"(r) : "l"(a), "l"(b), "l"(c)); return r;
}
static __device__ __forceinline__ uint64_t prsqrt(uint64_t m) {
    float a, b; funpack(m, a, b);
    float ra, rb;
    asm("rsqrt.approx.f32 %0,%1;" : "=f"(ra) : "f"(a));
    asm("rsqrt.approx.f32 %0,%1;" : "=f"(rb) : "f"(b));
    return fpack(ra, rb);
}

// ---------------------------------------------------------------------------
// Fused kernel, 512 blocks x 256 threads, 2 batches per block.
// Thread decomposition: bb = tid>>7 (batch in block), r = tid&127,
// c = r&3 (pair-chunk lane), tg = r>>2 -> timesteps {2tg, 2tg+1}.
// Thread iterates pairs p = 4i+c (i = 0..31); each iteration: one 32B
// neighbour record (2x LDS.128, zero repack) feeds BOTH timesteps:
// 2 x 16 packed f32x2 fma-pipe ops + 4 MUFU.RSQ.
// Math per (t, pair):
//   dx=px-nx, dy=py-ny; r2=dx^2+dy^2; x_=ca*dx+sa*dy; x2=x_^2; y2=r2-x2;
//   den=x2^3+y2^3+6; w=rsqrt(den^2*r2);     (MASS folded into finalize)
//   ex+=w*dx, ey+=w*dy                      (atan2 trig & signs cancel)
// v identical across the 4 c-lanes -> warp-sum overcounts 4x; folded into
// the finalize constant together with MASS.
// ---------------------------------------------------------------------------
__global__ __launch_bounds__(NTHR, 4)
void fused_kernel(const float* __restrict__ out,   // (PRE, BATCH, 2)
                  const float* __restrict__ tgt,   // (PRE, BATCH, 2)
                  const float* __restrict__ nb,    // (BATCH, NNB, 5)
                  float* __restrict__ dst)
{
    __shared__ ulonglong2 s_xy[BPB][NPAIR]; // {fpack(-nx0,-nx1), fpack(-ny0,-ny1)}
    __shared__ ulonglong2 s_cs[BPB][NPAIR]; // {fpack( ca0, ca1), fpack( sa0, sa1)}
    __shared__ float s_red[16];

    const int tid = threadIdx.x;
    const int b0  = blockIdx.x * BPB;

    // ---- MSE slice: one float per thread; 512*256 = 131072 = PRE*BATCH*2 ----
    float msum;
    {
        const int g = blockIdx.x * NTHR + tid;
        const float d = out[g] - tgt[g];
        msum = d * d;
    }

    // ---- stage neighbours: 256 pair-records, one per thread ----
    {
        const int sb = tid >> 7;          // batch in block
        const int p  = tid & (NPAIR - 1);
        const float* q = nb + ((size_t)(b0 + sb) * NNB + 2 * p) * 5;
        const float nx0 = q[0], ny0 = q[1], a0 = q[4];
        const float nx1 = q[5], ny1 = q[6], a1 = q[9];
        float sa0, ca0, sa1, ca1;
        __sincosf(a0, &sa0, &ca0);
        __sincosf(a1, &sa1, &ca1);
        ulonglong2 xy, cs;
        xy.x = fpack(-nx0, -nx1);
        xy.y = fpack(-ny0, -ny1);
        cs.x = fpack( ca0,  ca1);
        cs.y = fpack( sa0,  sa1);
        s_xy[sb][p] = xy;
        s_cs[sb][p] = cs;
    }
    __syncthreads();

    const int bb = tid >> 7;          // warp-uniform (warps 0-3 / 4-7)
    const int r  = tid & 127;
    const int c  = r & 3;             // pair-chunk lane
    const int tg = r >> 2;            // timestep pair 0..31
    const int b  = b0 + bb;

    const float2 pa = ((const float2*)out)[(size_t)(2 * tg)     * BATCH + b];
    const float2 pb = ((const float2*)out)[(size_t)(2 * tg + 1) * BATCH + b];
    const uint64_t pxa = fpack(pa.x, pa.x), pya = fpack(pa.y, pa.y);
    const uint64_t pxb = fpack(pb.x, pb.x), pyb = fpack(pb.y, pb.y);
    const uint64_t six2  = fpack(6.0f, 6.0f);
    const uint64_t mone2 = fpack(-1.0f, -1.0f);

    uint64_t axa = 0ull, aya = 0ull;  // (+0.0f, +0.0f)
    uint64_t axb = 0ull, ayb = 0ull;

    #pragma unroll 4
    for (int i = 0; i < NPAIR / 4; ++i) {
        const int p = (i << 2) | c;
        const ulonglong2 xy = s_xy[bb][p];
        const ulonglong2 cs = s_cs[bb][p];

        {   // timestep 2*tg
            const uint64_t dx = padd(pxa, xy.x);
            const uint64_t dy = padd(pya, xy.y);
            const uint64_t r2 = pfma(dx, dx, pmul(dy, dy));
            const uint64_t x_ = pfma(cs.x, dx, pmul(cs.y, dy));
            const uint64_t x2 = pmul(x_, x_);
            const uint64_t y2 = pfma(x2, mone2, r2);
            const uint64_t den = pfma(pmul(x2, x2), x2,
                                 pfma(pmul(y2, y2), y2, six2));
            const uint64_t w = prsqrt(pmul(pmul(den, den), r2));
            axa = pfma(w, dx, axa);
            aya = pfma(w, dy, aya);
        }
        {   // timestep 2*tg + 1
            const uint64_t dx = padd(pxb, xy.x);
            const uint64_t dy = padd(pyb, xy.y);
            const uint64_t r2 = pfma(dx, dx, pmul(dy, dy));
            const uint64_t x_ = pfma(cs.x, dx, pmul(cs.y, dy));
            const uint64_t x2 = pmul(x_, x_);
            const uint64_t y2 = pfma(x2, mone2, r2);
            const uint64_t den = pfma(pmul(x2, x2), x2,
                                 pfma(pmul(y2, y2), y2, six2));
            const uint64_t w = prsqrt(pmul(pmul(den, den), r2));
            axb = pfma(w, dx, axb);
            ayb = pfma(w, dy, ayb);
        }
    }

    // combine packed halves, reduce over the 4 c-lanes
    float t0, t1;
    funpack(axa, t0, t1); float exa = t0 + t1;
    funpack(aya, t0, t1); float eya = t0 + t1;
    funpack(axb, t0, t1); float exb = t0 + t1;
    funpack(ayb, t0, t1); float eyb = t0 + t1;
    #pragma unroll
    for (int o = 1; o <= 2; o <<= 1) {
        exa += __shfl_xor_sync(0xffffffffu, exa, o);
        eya += __shfl_xor_sync(0xffffffffu, eya, o);
        exb += __shfl_xor_sync(0xffffffffu, exb, o);
        eyb += __shfl_xor_sync(0xffffffffu, eyb, o);
    }

    // identical on 4 c-lanes -> warp sum overcounts 4x (folded in finalize)
    float v = sqrtf(fmaf(exa, exa, eya * eya))
            + sqrtf(fmaf(exb, exb, eyb * eyb));

    #pragma unroll
    for (int o = 16; o; o >>= 1) {
        v    += __shfl_xor_sync(0xffffffffu, v,    o);
        msum += __shfl_xor_sync(0xffffffffu, msum, o);
    }
    if ((tid & 31) == 0) {
        s_red[(tid >> 5) * 2 + 0] = v;
        s_red[(tid >> 5) * 2 + 1] = msum;
    }
    __syncthreads();

    if (tid == 0) {
        float fv = 0.0f, fm = 0.0f;
        #pragma unroll
        for (int w8 = 0; w8 < 8; ++w8) {
            fv += s_red[w8 * 2 + 0];
            fm += s_red[w8 * 2 + 1];
        }
        atomicAdd(&g_acc[0], fv);
        atomicAdd(&g_acc[1], fm);
        __threadfence();
        const unsigned rr = atomicAdd(&g_cnt, 1u);
        if (rr == (unsigned)(NBLK - 1)) {
            __threadfence();
            const float fe = *((volatile float*)&g_acc[0]);   // 4x, /MASS
            const float mm = *((volatile float*)&g_acc[1]);
            dst[0] = mm * (1.0f / (float)(PRE * BATCH * 2))
                   + fe * (MASSF / (4.0f * (float)(PRE * BATCH)));
            g_acc[0] = 0.0f;
            g_acc[1] = 0.0f;
            __threadfence();
            g_cnt = 0;
        }
    }
}

extern "C" void kernel_launch(void* const* d_in, const int* in_sizes, int n_in,
                              void* d_out, int out_size)
{
    const float* output     = (const float*)d_in[0];   // (64, 1024, 2)
    const float* target     = (const float*)d_in[1];   // (64, 1024, 2)
    const float* neighbours = (const float*)d_in[2];   // (1024, 256, 5)
    float* dst = (float*)d_out;

    fused_kernel<<<NBLK, NTHR>>>(output, target, neighbours, dst);
}